// round 16
// baseline (speedup 1.0000x reference)
#include <cuda_runtime.h>
#include <cuda_fp16.h>
#include <math.h>
#include <stdint.h>

// Problem constants
#define BATCH 4
#define TSEQ  1024
#define NEC   1024
#define NH    16
#define HSZ   64
#define MT    (BATCH*TSEQ)      // 4096 rows
#define EPSGN 0.00064f
#define NM    ((size_t)NEC*NEC) // 1M
#define HIDW  ((size_t)128*NEC) // one hidden weight slice
#define HME   ((size_t)MT*128)  // hidden matrix elems

// ---------------------------------------------------------------------------
// Scratch (device globals)
// ---------------------------------------------------------------------------
__device__ float    g_xx   [(size_t)MT*NEC];
__device__ uint32_t g_mixpk[(size_t)MT*NEC];   // packed (hi,lo) mix
__device__ float    g_hpart[4][HME];           // maa split-K partials
__device__ float    g_hmaa [HME];
__device__ float    g_hgate[HME];
__device__ float    g_hwaa [HME];              // decay(0:64) aaa(64:80) ma(80:96)
__device__ float    g_hk   [HME];              // kkk(0:16) mk(16:32)
__device__ uint32_t g_xm   [4][(size_t)MT*NEC]; // all packed (hi,lo) half2
__device__ __half   g_whalf[4*NM];             // Wr,Wk,Wv,Wo plain fp16
__device__ __half   g_whid [4*HIDW];           // hidden w1 slices fp16 (3) + maa_w1 (1)
__device__ uint32_t g_zpk  [(size_t)MT*NEC];
__device__ float    g_r    [(size_t)MT*NEC];
__device__ float    g_gg   [(size_t)MT*NEC];
__device__ float    g_k    [(size_t)MT*NEC];
__device__ float    g_v    [(size_t)MT*NEC];
__device__ float    g_w    [(size_t)MT*NEC];
__device__ float    g_kk   [(size_t)MT*NEC];
__device__ float    g_b    [(size_t)MT*NEC];
__device__ float    g_y    [(size_t)MT*NEC];

// ---------------------------------------------------------------------------
// helpers
// ---------------------------------------------------------------------------
__device__ __forceinline__ uint32_t packf(float v){
    __half hi = __float2half_rn(v);
    __half lo = __float2half_rn(v - __half2float(hi));
    __half2 h2 = __halves2half2(hi, lo);
    return *reinterpret_cast<uint32_t*>(&h2);
}
__device__ __forceinline__ void mma_f16(float* c, const uint32_t* a, const uint32_t* b){
    asm volatile("mma.sync.aligned.m16n8k16.row.col.f32.f16.f16.f32 "
        "{%0,%1,%2,%3},{%4,%5,%6,%7},{%8,%9},{%0,%1,%2,%3};\n"
        : "+f"(c[0]), "+f"(c[1]), "+f"(c[2]), "+f"(c[3])
        : "r"(a[0]), "r"(a[1]), "r"(a[2]), "r"(a[3]), "r"(b[0]), "r"(b[1]));
}
__device__ __forceinline__ void cpa16(uint32_t dst, const void* src){
    asm volatile("cp.async.cg.shared.global [%0],[%1],16;\n"::"r"(dst),"l"(src));
}
__device__ __forceinline__ void cpa4(uint32_t dst, const void* src){
    asm volatile("cp.async.ca.shared.global [%0],[%1],4;\n"::"r"(dst),"l"(src));
}
#define CP_COMMIT() asm volatile("cp.async.commit_group;\n")
#define CP_WAIT0()  asm volatile("cp.async.wait_group 0;\n")
#define CP_WAIT1()  asm volatile("cp.async.wait_group 1;\n")

__device__ __forceinline__ float sigm(float u){ return 1.f/(1.f+expf(-u)); }

// ---------------------------------------------------------------------------
// Token shift (float4); mix written packed
// ---------------------------------------------------------------------------
__global__ void shift_kernel(const float* __restrict__ x,
                             const float* __restrict__ tmaax,
                             float* __restrict__ xx,
                             uint32_t* __restrict__ mixpk)
{
    size_t i4 = (size_t)blockIdx.x * blockDim.x + threadIdx.x;
    if (i4 >= (size_t)MT * NEC / 4) return;
    size_t idx = i4 * 4;
    int c = (int)(idx % NEC);
    size_t row = idx / NEC;
    int t = (int)(row % TSEQ);
    float4 xv = *(const float4*)&x[idx];
    float4 xp = (t > 0) ? *(const float4*)&x[idx - NEC] : make_float4(0,0,0,0);
    float4 tm = *(const float4*)&tmaax[c];
    float4 d  = make_float4(xp.x-xv.x, xp.y-xv.y, xp.z-xv.z, xp.w-xv.w);
    *(float4*)&xx[idx] = d;
    uint4 m;
    m.x = packf(fmaf(d.x, tm.x, xv.x));
    m.y = packf(fmaf(d.y, tm.y, xv.y));
    m.z = packf(fmaf(d.z, tm.z, xv.z));
    m.w = packf(fmaf(d.w, tm.w, xv.w));
    *(uint4*)&mixpk[idx] = m;
}

// ---------------------------------------------------------------------------
// Weight pack: Wr/Wk/Wv/Wo -> fp16 (half2 stores)
// ---------------------------------------------------------------------------
__global__ void wpack_kernel(const float* __restrict__ Wr, const float* __restrict__ Wk,
                             const float* __restrict__ Wv, const float* __restrict__ Wo,
                             __half* __restrict__ whalf)
{
    size_t i = (size_t)blockIdx.x * blockDim.x + threadIdx.x;   // 2 elems each
    if (i >= 2*NM) return;
    int seg = (int)(i >> 19);
    size_t off2 = (i & ((NM>>1) - 1)) * 2;
    const float* src = (seg==0) ? Wr : (seg==1) ? Wk : (seg==2) ? Wv : Wo;
    float2 v = *(const float2*)&src[off2];
    __half2 h = __halves2half2(__float2half_rn(v.x), __float2half_rn(v.y));
    *(__half2*)&whalf[(size_t)seg*NM + off2] = h;
}

// ---------------------------------------------------------------------------
// Hidden weight pack: 4 padded slices [128][1024] fp16
// ---------------------------------------------------------------------------
__global__ void wpack2_kernel(const float* __restrict__ gate_w1,
                              const float* __restrict__ decay_w1,
                              const float* __restrict__ aaa_w1,
                              const float* __restrict__ ma_w1,
                              const float* __restrict__ kkk_w1,
                              const float* __restrict__ mk_w1,
                              const float* __restrict__ maa_w1,
                              __half* __restrict__ whid)
{
    size_t i = (size_t)blockIdx.x * blockDim.x + threadIdx.x;
    if (i >= 4*HIDW) return;
    int slice = (int)(i / HIDW);
    size_t rem = i - (size_t)slice*HIDW;
    int row = (int)(rem >> 10);
    float v = 0.f;
    if (slice == 0) v = gate_w1[rem];
    else if (slice == 1) {
        if (row < 64)      v = decay_w1[rem];
        else if (row < 80) v = aaa_w1[rem - (size_t)64*NEC];
        else if (row < 96) v = ma_w1[rem - (size_t)80*NEC];
    } else if (slice == 2) {
        if (row < 16)      v = kkk_w1[rem];
        else if (row < 32) v = mk_w1[rem - (size_t)16*NEC];
    } else {
        v = maa_w1[rem];
    }
    whid[i] = __float2half_rn(v);
}

// ---------------------------------------------------------------------------
// Reduce + tanh for maa split-K partials
// ---------------------------------------------------------------------------
__global__ void hred_kernel(const float* __restrict__ hpart,
                            float* __restrict__ hmaa)
{
    size_t i4 = (size_t)blockIdx.x * blockDim.x + threadIdx.x;
    if (i4 >= HME/4) return;
    size_t idx = i4 * 4;
    float4 p0 = *(const float4*)&hpart[0*HME + idx];
    float4 p1 = *(const float4*)&hpart[1*HME + idx];
    float4 p2 = *(const float4*)&hpart[2*HME + idx];
    float4 p3 = *(const float4*)&hpart[3*HME + idx];
    float4 o;
    o.x = tanhf((p0.x+p1.x)+(p2.x+p3.x));
    o.y = tanhf((p0.y+p1.y)+(p2.y+p3.y));
    o.z = tanhf((p0.z+p1.z)+(p2.z+p3.z));
    o.w = tanhf((p0.w+p1.w)+(p2.w+p3.w));
    *(float4*)&hmaa[idx] = o;
}

// ---------------------------------------------------------------------------
// 2-product NT GEMM: grid (gx, 32, nz + maybe-hidden).
// ---------------------------------------------------------------------------
#define G5_LDSW 36
#define G5_AW   (128*G5_LDSW)
#define G5_LDHB 40
#define G5_BW   (128*G5_LDHB/2)
#define G5_STG  (G5_AW + G5_BW)

struct G5Args {
    const uint32_t* A[3]; const __half* B[3]; float* C[3];
    const uint32_t* HA[4]; const __half* HB[4]; float* HC[4]; int tanhN[4];
    int nz;
};

__global__ __launch_bounds__(256, 2)
void gemm_tc5(G5Args args, int K, int ldab)
{
    extern __shared__ uint32_t sm5[];
    const int z = blockIdx.z;
    const uint32_t* Apk; const __half* Bhp; float* C;
    int bn0, ldc, tanhN;
    if (z < args.nz) {
        Apk = args.A[z]; Bhp = args.B[z]; C = args.C[z];
        bn0 = blockIdx.x*128; ldc = NEC; tanhN = -1;
    } else {
        int s = blockIdx.x;
        if (s >= 4) return;
        Apk = args.HA[s]; Bhp = args.HB[s]; C = args.HC[s];
        if (!C) return;
        bn0 = 0; ldc = 128; tanhN = args.tanhN[s];
    }
    const int tid = threadIdx.x;
    const int bm0 = blockIdx.y*128;
    const int warp = tid>>5, lane = tid&31, grp = lane>>2, q = lane&3;
    const int wm = (warp&1)*64, wn = (warp>>1)*32;
    const uint32_t sbase = (uint32_t)__cvta_generic_to_shared(sm5);

    float acc[4][4][4];
    #pragma unroll
    for (int mi=0;mi<4;mi++)
        #pragma unroll
        for (int ni=0;ni<4;ni++)
            #pragma unroll
            for (int e=0;e<4;e++) acc[mi][ni][e]=0.f;

    const uint32_t* asrc[4]; uint32_t adst[4];
    #pragma unroll
    for (int l = 0; l < 4; l++) {
        int idx = tid + l*256;
        int r = idx >> 3, c4 = idx & 7;
        asrc[l] = Apk + (size_t)(bm0+r)*ldab + c4*4;
        adst[l] = sbase + (uint32_t)(r*G5_LDSW + c4*4)*4;
    }
    const __half* bsrc[2]; uint32_t bdst[2];
    #pragma unroll
    for (int l = 0; l < 2; l++) {
        int idx = tid + l*256;
        int r = idx >> 2, c4 = idx & 3;
        bsrc[l] = Bhp + (size_t)(bn0+r)*ldab + c4*8;
        bdst[l] = sbase + G5_AW*4 + (uint32_t)(r*G5_LDHB + c4*8)*2;
    }

#define G5_LOAD(st, kb) do {                                   \
        uint32_t _o = (st)*G5_STG*4;                           \
        _Pragma("unroll")                                      \
        for (int l = 0; l < 4; l++)                            \
            cpa16(adst[l] + _o, asrc[l] + (kb));               \
        _Pragma("unroll")                                      \
        for (int l = 0; l < 2; l++)                            \
            cpa16(bdst[l] + _o, bsrc[l] + (kb));               \
    } while(0)

    G5_LOAD(0, 0); CP_COMMIT();

    int p = 0;
    for (int kb = 0; kb < K; kb += 32) {
        CP_WAIT0();
        __syncthreads();
        if (kb + 32 < K) { G5_LOAD(p^1, kb+32); CP_COMMIT(); }

        const uint32_t* SA = sm5 + p*G5_STG;
        const __half*   SB = (const __half*)(sm5 + p*G5_STG + G5_AW);

        #pragma unroll
        for (int kc = 0; kc < 32; kc += 16) {
            uint32_t ah[4][4], al[4][4], bh[4][2];
            #pragma unroll
            for (int mi = 0; mi < 4; mi++) {
                int r0 = (wm + mi*16 + grp)*G5_LDSW + kc + 2*q;
                uint2 w0 = *(const uint2*)&SA[r0];
                uint2 w1 = *(const uint2*)&SA[r0 + 8*G5_LDSW];
                uint2 w2 = *(const uint2*)&SA[r0 + 8];
                uint2 w3 = *(const uint2*)&SA[r0 + 8*G5_LDSW + 8];
                ah[mi][0]=__byte_perm(w0.x,w0.y,0x5410); al[mi][0]=__byte_perm(w0.x,w0.y,0x7632);
                ah[mi][1]=__byte_perm(w1.x,w1.y,0x5410); al[mi][1]=__byte_perm(w1.x,w1.y,0x7632);
                ah[mi][2]=__byte_perm(w2.x,w2.y,0x5410); al[mi][2]=__byte_perm(w2.x,w2.y,0x7632);
                ah[mi][3]=__byte_perm(w3.x,w3.y,0x5410); al[mi][3]=__byte_perm(w3.x,w3.y,0x7632);
            }
            #pragma unroll
            for (int ni = 0; ni < 4; ni++) {
                int c0 = (wn + ni*8 + grp)*G5_LDHB + kc + 2*q;
                bh[ni][0] = *(const uint32_t*)&SB[c0];
                bh[ni][1] = *(const uint32_t*)&SB[c0 + 8];
            }
            #pragma unroll
            for (int mi = 0; mi < 4; mi++)
                #pragma unroll
                for (int ni = 0; ni < 4; ni++) {
                    mma_f16(acc[mi][ni], ah[mi], bh[ni]);
                    mma_f16(acc[mi][ni], al[mi], bh[ni]);
                }
        }
        __syncthreads();
        p ^= 1;
    }

    #pragma unroll
    for (int mi = 0; mi < 4; mi++) {
        int row0 = bm0 + wm + mi*16 + grp;
        #pragma unroll
        for (int ni = 0; ni < 4; ni++) {
            int col = bn0 + wn + ni*8 + 2*q;
            float e0 = acc[mi][ni][0], e1 = acc[mi][ni][1];
            float e2 = acc[mi][ni][2], e3 = acc[mi][ni][3];
            if (tanhN >= 0) {
                if (col   < tanhN) { e0 = tanhf(e0); e2 = tanhf(e2); }
                if (col+1 < tanhN) { e1 = tanhf(e1); e3 = tanhf(e3); }
            }
            *(float2*)&C[(size_t)row0*ldc + col]     = make_float2(e0, e1);
            *(float2*)&C[(size_t)(row0+8)*ldc + col] = make_float2(e2, e3);
        }
    }
#undef G5_LOAD
}

// ---------------------------------------------------------------------------
// Fused xm kernel: val = x + xx*(Ag @ Bg + time_maa[g]); all groups packed.
// ---------------------------------------------------------------------------
__global__ __launch_bounds__(256, 2)
void xm_kernel(const float* __restrict__ hmaa,
               const float* __restrict__ maa_w2,
               const float* __restrict__ x,
               const float* __restrict__ xx,
               const float* __restrict__ time_maa,
               uint32_t* __restrict__ xmbase)
{
    constexpr int BM=128, BN=128, BK=32;
    __shared__ float As[BK][BM+1];
    __shared__ float Bs[BK][BN];
    const int g = blockIdx.z;
    const float* A = hmaa + g*32;
    const float* B = maa_w2 + (size_t)g*32*NEC;
    uint32_t* C = xmbase + (size_t)g*MT*NEC;
    const float* tm = time_maa + g*NEC;
    const int bm0 = blockIdx.y*BM, bn0 = blockIdx.x*BN;
    const int tid = threadIdx.x;
    const int tx = tid & 15, ty = tid >> 4;

    float acc[8][8];
    #pragma unroll
    for (int i=0;i<8;i++)
        #pragma unroll
        for (int j=0;j<8;j++) acc[i][j]=0.f;

    #pragma unroll
    for (int l = 0; l < 4; l++) {
        int idx = tid + l*256;
        int r = idx >> 3, c = (idx & 7)*4;
        float4 val = *(const float4*)(A + (size_t)(bm0+r)*128 + c);
        As[c+0][r]=val.x; As[c+1][r]=val.y; As[c+2][r]=val.z; As[c+3][r]=val.w;
    }
    #pragma unroll
    for (int l = 0; l < 4; l++) {
        int idx = tid + l*256;
        int r = idx >> 5, c = (idx & 31)*4;
        *(float4*)&Bs[r][c] = *(const float4*)(B + (size_t)r*NEC + bn0 + c);
    }
    __syncthreads();
    #pragma unroll
    for (int kk = 0; kk < BK; kk++) {
        float rm[8], rn[8];
        #pragma unroll
        for (int i=0;i<8;i++) rm[i] = As[kk][ty*8+i];
        #pragma unroll
        for (int j=0;j<8;j++) rn[j] = Bs[kk][tx*8+j];
        #pragma unroll
        for (int i=0;i<8;i++)
            #pragma unroll
            for (int j=0;j<8;j++) acc[i][j] = fmaf(rm[i], rn[j], acc[i][j]);
    }
    #pragma unroll
    for (int i=0;i<8;i++) {
        int row = bm0 + ty*8 + i;
        #pragma unroll
        for (int j=0;j<8;j+=2) {
            int col = bn0 + tx*8 + j;
            size_t idx = (size_t)row*NEC + col;
            float2 xv = *(const float2*)&x[idx];
            float2 dv = *(const float2*)&xx[idx];
            float v0 = fmaf(dv.x, acc[i][j]   + tm[col],   xv.x);
            float v1 = fmaf(dv.y, acc[i][j+1] + tm[col+1], xv.y);
            *(uint2*)&C[idx] = make_uint2(packf(v0), packf(v1));
        }
    }
}

// ---------------------------------------------------------------------------
// Fused post kernel: replaces lora_nn + prep.
// Block = 128 rows x 64 cols (one head wide), 256 threads, patch 8x4.
// Phases: a, ma, wraw, mk, kkraw(+k), gg; writes gg, w, k, kk, b.
// ---------------------------------------------------------------------------
__device__ __forceinline__ void pg_phase(
    float acc[8][4],
    const float* __restrict__ A, int koff,
    const float* __restrict__ B, int K,
    int bm0, int bn0, int tid, int tx, int ty,
    float (*As)[132], float (*Bs)[68])
{
    #pragma unroll
    for (int i=0;i<8;i++)
        #pragma unroll
        for (int j=0;j<4;j++) acc[i][j]=0.f;
    for (int kb = 0; kb < K; kb += 16) {
        #pragma unroll
        for (int l = 0; l < 2; l++) {
            int idx = tid + l*256;
            int r = idx >> 2, c = (idx & 3)*4;
            float4 v = *(const float4*)(A + (size_t)(bm0+r)*128 + koff + kb + c);
            As[c+0][r]=v.x; As[c+1][r]=v.y; As[c+2][r]=v.z; As[c+3][r]=v.w;
        }
        {
            int r = tid >> 4, c = (tid & 15)*4;
            *(float4*)&Bs[r][c] = *(const float4*)(B + (size_t)(kb+r)*NEC + bn0 + c);
        }
        __syncthreads();
        #pragma unroll
        for (int kq = 0; kq < 16; kq++) {
            float4 m0 = *(const float4*)&As[kq][ty*8];
            float4 m1 = *(const float4*)&As[kq][ty*8+4];
            float4 rn = *(const float4*)&Bs[kq][tx*4];
            float rm[8] = {m0.x,m0.y,m0.z,m0.w,m1.x,m1.y,m1.z,m1.w};
            #pragma unroll
            for (int i=0;i<8;i++) {
                acc[i][0] = fmaf(rm[i], rn.x, acc[i][0]);
                acc[i][1] = fmaf(rm[i], rn.y, acc[i][1]);
                acc[i][2] = fmaf(rm[i], rn.z, acc[i][2]);
                acc[i][3] = fmaf(rm[i], rn.w, acc[i][3]);
            }
        }
        __syncthreads();
    }
}

__global__ __launch_bounds__(256)
void post_kernel(const float* __restrict__ hgate,
                 const float* __restrict__ hwaa,
                 const float* __restrict__ hk,
                 const float* __restrict__ gate_w2,
                 const float* __restrict__ decay_w2,
                 const float* __restrict__ aaa_w2,
                 const float* __restrict__ ma_w2,
                 const float* __restrict__ kkk_w2,
                 const float* __restrict__ mk_w2,
                 const float* __restrict__ td,
                 const float* __restrict__ taa,
                 const float* __restrict__ tma,
                 const float* __restrict__ tmk,
                 float* __restrict__ gg,
                 float* __restrict__ w,
                 float* __restrict__ k,
                 float* __restrict__ kk,
                 float* __restrict__ b)
{
    __shared__ __align__(16) float As[16][132];
    __shared__ __align__(16) float Bs[16][68];
    const int tid = threadIdx.x;
    const int tx = tid & 15, ty = tid >> 4;
    const int bm0 = blockIdx.y*128, bn0 = blockIdx.x*64;
    const int col0 = bn0 + tx*4;

    float acc[8][4], aR[8][4], coef[8][4], wraw[8][4];

    // 1) a = sigmoid(taa + hwaa[:,64:80] @ aaa_w2)
    pg_phase(acc, hwaa, 64, aaa_w2, 16, bm0, bn0, tid, tx, ty, As, Bs);
    #pragma unroll
    for (int i=0;i<8;i++)
        #pragma unroll
        for (int j=0;j<4;j++) aR[i][j] = sigm(taa[col0+j] + acc[i][j]);

    // 2) ma -> coef = ma + a*(1-ma)
    pg_phase(acc, hwaa, 80, ma_w2, 16, bm0, bn0, tid, tx, ty, As, Bs);
    #pragma unroll
    for (int i=0;i<8;i++)
        #pragma unroll
        for (int j=0;j<4;j++) {
            float m = sigm(tma[col0+j] + acc[i][j]);
            coef[i][j] = m + aR[i][j]*(1.f - m);
        }

    // 3) wraw = -softplus(-(td + hwaa[:,0:64] @ decay_w2)) - 0.5
    pg_phase(acc, hwaa, 0, decay_w2, 64, bm0, bn0, tid, tx, ty, As, Bs);
    #pragma unroll
    for (int i=0;i<8;i++)
        #pragma unroll
        for (int j=0;j<4;j++) {
            float tt = -(td[col0+j] + acc[i][j]);
            float sp = (tt > 15.f) ? tt : log1pf(expf(tt));
            wraw[i][j] = -sp - 0.5f;
        }

    // 4) mk -> kmul = coef*exp(wraw*mk); w = exp(-exp(wraw))
    pg_phase(acc, hk, 16, mk_w2, 16, bm0, bn0, tid, tx, ty, As, Bs);
    #pragma unroll
    for (int i=0;i<8;i++) {
        int row = bm0 + ty*8 + i;
        float4 wo;
        #pragma unroll
        for (int j=0;j<4;j++) {
            float m = sigm(tmk[col0+j] + acc[i][j]);
            coef[i][j] = coef[i][j] * expf(wraw[i][j]*m);   // coef becomes kmul
            ((float*)&wo)[j] = expf(-expf(wraw[i][j]));
        }
        *(float4*)&w[(size_t)row*NEC + col0] = wo;
    }
    // wraw now free (reuse for kload)

    // 5) kkraw -> kk = normalize(kkraw + k); b = -kk*a; k = k*kmul
    pg_phase(acc, hk, 0, kkk_w2, 16, bm0, bn0, tid, tx, ty, As, Bs);
    #pragma unroll
    for (int i=0;i<8;i++) {
        int row = bm0 + ty*8 + i;
        float4 kv = *(const float4*)&k[(size_t)row*NEC + col0];
        wraw[i][0]=kv.x; wraw[i][1]=kv.y; wraw[i][2]=kv.z; wraw[i][3]=kv.w;
        #pragma unroll
        for (int j=0;j<4;j++) acc[i][j] += wraw[i][j];      // kkq
    }
    #pragma unroll
    for (int i=0;i<8;i++) {
        int row = bm0 + ty*8 + i;
        float ss = acc[i][0]*acc[i][0] + acc[i][1]*acc[i][1]
                 + acc[i][2]*acc[i][2] + acc[i][3]*acc[i][3];
        ss += __shfl_xor_sync(0xffffffffu, ss, 1);
        ss += __shfl_xor_sync(0xffffffffu, ss, 2);
        ss += __shfl_xor_sync(0xffffffffu, ss, 4);
        ss += __shfl_xor_sync(0xffffffffu, ss, 8);
        float inv = 1.f / fmaxf(sqrtf(ss), 1e-12f);
        float4 kko, bo, ko;
        #pragma unroll
        for (int j=0;j<4;j++) {
            float n = acc[i][j]*inv;
            ((float*)&kko)[j] = n;
            ((float*)&bo)[j]  = -n*aR[i][j];
            ((float*)&ko)[j]  = wraw[i][j]*coef[i][j];
        }
        *(float4*)&kk[(size_t)row*NEC + col0] = kko;
        *(float4*)&b [(size_t)row*NEC + col0] = bo;
        *(float4*)&k [(size_t)row*NEC + col0] = ko;
    }

    // 6) gg = hgate @ gate_w2
    pg_phase(acc, hgate, 0, gate_w2, 128, bm0, bn0, tid, tx, ty, As, Bs);
    #pragma unroll
    for (int i=0;i<8;i++) {
        int row = bm0 + ty*8 + i;
        *(float4*)&gg[(size_t)row*NEC + col0] =
            make_float4(acc[i][0], acc[i][1], acc[i][2], acc[i][3]);
    }
}

// ---------------------------------------------------------------------------
// warp sum
// ---------------------------------------------------------------------------
__device__ __forceinline__ float warp_sum(float v)
{
    #pragma unroll
    for (int o = 16; o > 0; o >>= 1) v += __shfl_xor_sync(0xffffffffu, v, o);
    return v;
}

// ---------------------------------------------------------------------------
// RWKV7 recurrence v5: 2 blocks per head; 32 rows x 8-way column split;
// 3-PAIR cp.async ring, 2 steps per iteration.
// ---------------------------------------------------------------------------
__device__ __forceinline__ void wkv7_step(const float* __restrict__ bb,
                                          float* __restrict__ s,
                                          int il, int qd,
                                          float* __restrict__ yout)
{
    const int co = qd*8;
    const float4* q4 = (const float4*)(bb +   0 + co);
    const float4* w4 = (const float4*)(bb +  64 + co);
    const float4* k4 = (const float4*)(bb + 128 + co);
    const float4* a4 = (const float4*)(bb + 192 + co);
    const float4* b4 = (const float4*)(bb + 256 + co);
    float vi = bb[320 + il];

    float4 av0 = a4[0], av1 = a4[1];
    float sa0 = fmaf(s[0], av0.x, s[4]*av1.x);
    float sa1 = fmaf(s[1], av0.y, s[5]*av1.y);
    float sa2 = fmaf(s[2], av0.z, s[6]*av1.z);
    float sa3 = fmaf(s[3], av0.w, s[7]*av1.w);
    float sa = (sa0+sa1) + (sa2+sa3);
    sa += __shfl_xor_sync(0xffffffffu, sa, 1);
    sa += __shfl_xor_sync(0xffffffffu, sa, 2);
    sa += __shfl_xor_sync(0xffffffffu, sa, 4);

    float4 wv0 = w4[0], wv1 = w4[1];
    float4 kv0 = k4[0], kv1 = k4[1];
    float4 bv0 = b4[0], bv1 = b4[1];
    float4 qv0 = q4[0], qv1 = q4[1];

    float t0 = fmaf(s[0], wv0.x, fmaf(sa, bv0.x, vi*kv0.x));
    float t1 = fmaf(s[1], wv0.y, fmaf(sa, bv0.y, vi*kv0.y));
    float t2 = fmaf(s[2], wv0.z, fmaf(sa, bv0.z, vi*kv0.z));
    float t3 = fmaf(s[3], wv0.w, fmaf(sa, bv0.w, vi*kv0.w));
    float t4 = fmaf(s[4], wv1.x, fmaf(sa, bv1.x, vi*kv1.x));
    float t5 = fmaf(s[5], wv1.y, fmaf(sa, bv1.y, vi*kv1.y));
    float t6 = fmaf(s[6], wv1.z, fmaf(sa, bv1.z, vi*kv1.z));
    float t7 = fmaf(s[7], wv1.w, fmaf(sa, bv1.w, vi*kv1.w));
    s[0]=t0; s[1]=t1; s[2]=t2; s[3]=t3; s[4]=t4; s[5]=t5; s[6]=t6; s[7]=t7;

    float y0 = fmaf(t0, qv0.x, t4*qv1.x);
    float y1 = fmaf(t1, qv0.y, t5*qv1.y);
    float y2 = fmaf(t2, qv0.z, t6*qv1.z);
    float y3 = fmaf(t3, qv0.w, t7*qv1.w);
    float yi = (y0+y1) + (y2+y3);
    yi += __shfl_xor_sync(0xffffffffu, yi, 1);
    yi += __shfl_xor_sync(0xffffffffu, yi, 2);
    yi += __shfl_xor_sync(0xffffffffu, yi, 4);
    if (qd == 0) *yout = yi;
}

__global__ __launch_bounds__(256)
void wkv7_kernel(const float* __restrict__ q, const float* __restrict__ w,
                 const float* __restrict__ k, const float* __restrict__ v,
                 const float* __restrict__ a, const float* __restrict__ b,
                 float* __restrict__ y)
{
    const int blk = blockIdx.x;            // 0..127
    const int bh = blk >> 1, rh = blk & 1;
    const int batch = bh >> 4, h = bh & 15;
    const int tid = threadIdx.x;
    const int il = tid >> 3, qd = tid & 7;

    __shared__ __align__(16) float buf[3][704];

    float s[8];
    #pragma unroll
    for (int j = 0; j < 8; j++) s[j] = 0.f;

    const size_t base = (size_t)batch * TSEQ * NEC + (size_t)h * HSZ;

    const float* table[4] = {q, w, k, a};
    const float* s0 = table[tid>>6] + base + (tid & 63);
    const float* s1 = nullptr;
    if (tid < 64)       s1 = b + base + tid;
    else if (tid < 96)  s1 = v + base + rh*32 + (tid - 64);
    const uint32_t sb = (uint32_t)__cvta_generic_to_shared(buf);
    const uint32_t d0 = sb + (uint32_t)tid*4;
    const uint32_t d1 = sb + (uint32_t)(256 + tid)*4;
    const uint32_t PAIRB = 704*4;
    const uint32_t STEPB = 352*4;

    #pragma unroll
    for (int pr = 0; pr < 2; pr++) {
        size_t o = (size_t)(2*pr)*NEC;
        cpa4(d0 + pr*PAIRB, s0 + o);
        if (tid < 96) cpa4(d1 + pr*PAIRB, s1 + o);
        cpa4(d0 + pr*PAIRB + STEPB, s0 + o + NEC);
        if (tid < 96) cpa4(d1 + pr*PAIRB + STEPB, s1 + o + NEC);
        CP_COMMIT();
    }

    const size_t ybase = base + (size_t)rh*32 + il;

    int pp = 0;
    for (int t = 0; t < TSEQ; t += 2) {
        CP_WAIT1();
        __syncthreads();

        {
            int pf = pp + 2; if (pf >= 3) pf -= 3;
            if (t + 4 < TSEQ) {
                size_t o = (size_t)(t+4)*NEC;
                uint32_t db = (uint32_t)pf*PAIRB;
                cpa4(d0 + db, s0 + o);
                if (tid < 96) cpa4(d1 + db, s1 + o);
                cpa4(d0 + db + STEPB, s0 + o + NEC);
                if (tid < 96) cpa4(d1 + db + STEPB, s1 + o + NEC);
            }
            CP_COMMIT();
        }

        wkv7_step(&buf[pp][0],   s, il, qd, &y[ybase + (size_t)t*NEC]);
        wkv7_step(&buf[pp][352], s, il, qd, &y[ybase + (size_t)(t+1)*NEC]);

        if (++pp == 3) pp = 0;
    }
}

// ---------------------------------------------------------------------------
// GroupNorm + bonus + gate -> packed z
// ---------------------------------------------------------------------------
__global__ void gn_kernel(const float* __restrict__ y,
                          const float* __restrict__ r,
                          const float* __restrict__ k,
                          const float* __restrict__ v,
                          const float* __restrict__ gg,
                          const float* __restrict__ ln_w,
                          const float* __restrict__ ln_b,
                          const float* __restrict__ faaaa,
                          uint32_t* __restrict__ zpk)
{
    int m = blockIdx.x;
    int h = threadIdx.x >> 5;
    int lane = threadIdx.x & 31;
    size_t base = (size_t)m*NEC + h*HSZ;
    int c0 = h*HSZ + lane, c1 = c0 + 32;
    size_t i0 = base + lane, i1 = i0 + 32;

    float y0 = y[i0], y1 = y[i1];
    float mu = warp_sum(y0 + y1) * (1.f/64.f);
    float d0 = y0 - mu, d1 = y1 - mu;
    float var = warp_sum(d0*d0 + d1*d1) * (1.f/64.f);
    float rstd = rsqrtf(var + EPSGN);
    float yn0 = d0*rstd*ln_w[c0] + ln_b[c0];
    float yn1 = d1*rstd*ln_w[c1] + ln_b[c1];

    float r0 = r[i0], r1 = r[i1];
    float k0v = k[i0], k1v = k[i1];
    float rk = warp_sum(r0*k0v*faaaa[c0] + r1*k1v*faaaa[c1]);

    float v0 = v[i0], v1 = v[i1];
    zpk[i0] = packf((yn0 + rk*v0) * gg[i0]);
    zpk[i1] = packf((yn1 + rk*v1) * gg[i1]);
}

// ---------------------------------------------------------------------------
// Host side
// ---------------------------------------------------------------------------
extern "C" void kernel_launch(void* const* d_in, const int* in_sizes, int n_in,
                              void* d_out, int out_size)
{
    const float* x          = (const float*)d_in[0];
    const float* time_maa_x = (const float*)d_in[1];
    const float* time_maa   = (const float*)d_in[2];
    const float* maa_w1     = (const float*)d_in[3];
    const float* maa_w2     = (const float*)d_in[4];
    const float* decay_w1   = (const float*)d_in[5];
    const float* decay_w2   = (const float*)d_in[6];
    const float* aaa_w1     = (const float*)d_in[7];
    const float* aaa_w2     = (const float*)d_in[8];
    const float* kkk_w1     = (const float*)d_in[9];
    const float* kkk_w2     = (const float*)d_in[10];
    const float* gate_w1    = (const float*)d_in[11];
    const float* gate_w2    = (const float*)d_in[12];
    const float* ma_w1      = (const float*)d_in[13];
    const float* ma_w2      = (const float*)d_in[14];
    const float* mk_w1      = (const float*)d_in[15];
    const float* mk_w2      = (const float*)d_in[16];
    const float* time_decay = (const float*)d_in[17];
    const float* time_faaaa = (const float*)d_in[18];
    const float* time_aaaaa = (const float*)d_in[19];
    const float* time_misc_a= (const float*)d_in[20];
    const float* time_misc_k= (const float*)d_in[21];
    const float* Wr         = (const float*)d_in[22];
    const float* Wk         = (const float*)d_in[23];
    const float* Wv         = (const float*)d_in[24];
    const float* Wo         = (const float*)d_in[25];
    const float* ln_w       = (const float*)d_in[26];
    const float* ln_b       = (const float*)d_in[27];
    float* out = (float*)d_out;

    float *xx,*hpart,*hmaa,*hgate,*hwaa,*hk;
    uint32_t *mixpk,*xm,*zpk; __half *whalf,*whid;
    float *r,*gg,*k,*v,*w,*kk,*b,*y;
    cudaGetSymbolAddress((void**)&xx,   g_xx);
    cudaGetSymbolAddress((void**)&mixpk,g_mixpk);
    cudaGetSymbolAddress((void**)&hpart,g_hpart);
    cudaGetSymbolAddress((void**)&hmaa, g_hmaa);
    cudaGetSymbolAddress((void**)&hgate,g_hgate);
    cudaGetSymbolAddress((void**)&hwaa, g_hwaa);
    cudaGetSymbolAddress((void**)&hk,   g_hk);
    cudaGetSymbolAddress((void**)&xm,   g_xm);
    cudaGetSymbolAddress((void**)&whalf,g_whalf);
    cudaGetSymbolAddress((void**)&whid, g_whid);
    cudaGetSymbolAddress((void**)&zpk,  g_zpk);
    cudaGetSymbolAddress((void**)&r,    g_r);
    cudaGetSymbolAddress((void**)&gg,   g_gg);
    cudaGetSymbolAddress((void**)&k,    g_k);
    cudaGetSymbolAddress((void**)&v,    g_v);
    cudaGetSymbolAddress((void**)&w,    g_w);
    cudaGetSymbolAddress((void**)&kk,   g_kk);
    cudaGetSymbolAddress((void**)&b,    g_b);
    cudaGetSymbolAddress((void**)&y,    g_y);

    const size_t S = (size_t)MT*NEC;
    const uint32_t* xrg_pk = xm + 0*S;
    const uint32_t* xwa_pk = xm + 1*S;
    const uint32_t* xk_pk  = xm + 2*S;
    const uint32_t* xv_pk  = xm + 3*S;

    static bool attr_done = false;
    if (!attr_done) {
        cudaFuncSetAttribute(gemm_tc5, cudaFuncAttributeMaxDynamicSharedMemorySize,
                             2*G5_STG*4);
        attr_done = true;
    }
    const int g5_smem = 2*G5_STG*4;

    // 1) token shift (mix packed)
    shift_kernel<<<(unsigned)((S/4 + 255)/256), 256>>>(x, time_maa_x, xx, mixpk);

    // 2) weight packs
    wpack_kernel<<<(unsigned)((2*NM + 255)/256), 256>>>(Wr, Wk, Wv, Wo, whalf);
    wpack2_kernel<<<(unsigned)((4*HIDW + 255)/256), 256>>>(
        gate_w1, decay_w1, aaa_w1, ma_w1, kkk_w1, mk_w1, maa_w1, whid);

    // 3) maa hidden split-K 4 -> partials, reduce+tanh
    {
        G5Args ga = {};
        ga.nz = 0;
        for (int sK = 0; sK < 4; sK++) {
            ga.HA[sK] = mixpk + sK*256;
            ga.HB[sK] = whid + 3*HIDW + sK*256;
            ga.HC[sK] = hpart + (size_t)sK*HME;
            ga.tanhN[sK] = -1;
        }
        gemm_tc5<<<dim3(4, 32, 1), 256, g5_smem>>>(ga, 256, NEC);
    }
    hred_kernel<<<(unsigned)((HME/4 + 255)/256), 256>>>(hpart, hmaa);

    // 4) xm fused (4 groups, all packed)
    xm_kernel<<<dim3(8, MT/128, 4), 256>>>(hmaa, maa_w2, x, xx, time_maa, xm);

    // 5) mega GEMM: r,k,v (z 0-2) + hidden slices (z 3)
    {
        G5Args ga = {};
        ga.nz = 3;
        ga.A[0] = xrg_pk; ga.B[0] = whalf + 0*NM; ga.C[0] = r;
        ga.A[1] = xk_pk;  ga.B[1] = whalf + 1*NM; ga.C[1] = k;
        ga.A[2] = xv_pk;  ga.B[2] = whalf + 2*NM; ga.C[2] = v;
        ga.HA[0] = xrg_pk; ga.HB[0] = whid + 0*HIDW; ga.HC[0] = hgate; ga.tanhN[0] = 128;
        ga.HA[1] = xwa_pk; ga.HB[1] = whid + 1*HIDW; ga.HC[1] = hwaa;  ga.tanhN[1] = 64;
        ga.HA[2] = xk_pk;  ga.HB[2] = whid + 2*HIDW; ga.HC[2] = hk;    ga.tanhN[2] = 16;
        ga.HC[3] = nullptr;
        gemm_tc5<<<dim3(8, 32, 4), 256, g5_smem>>>(ga, NEC, NEC);
    }

    // 6) fused post (lora_nn second stage + prep)
    post_kernel<<<dim3(16, 32), 256>>>(
        hgate, hwaa, hk,
        gate_w2, decay_w2, aaa_w2, ma_w2, kkk_w2, mk_w2,
        time_decay, time_aaaaa, time_misc_a, time_misc_k,
        gg, w, k, kk, b);

    // 7) recurrence (pair-unrolled)
    wkv7_kernel<<<BATCH*NH*2, 256>>>(r, w, k, v, kk, b, y);

    // 8) groupnorm + bonus + gate -> packed z
    gn_kernel<<<MT, 512>>>(y, r, k, v, gg, ln_w, ln_b, time_faaaa, zpk);

    // 9) out = z @ Wo.T (2-product)
    {
        G5Args ga = {};
        ga.nz = 1;
        ga.A[0] = zpk; ga.B[0] = whalf + 3*NM; ga.C[0] = out;
        gemm_tc5<<<dim3(8, 32, 1), 256, g5_smem>>>(ga, NEC, NEC);
    }
}

// round 17
// speedup vs baseline: 1.0325x; 1.0325x over previous
#include <cuda_runtime.h>
#include <cuda_fp16.h>
#include <math.h>
#include <stdint.h>

// Problem constants
#define BATCH 4
#define TSEQ  1024
#define NEC   1024
#define NH    16
#define HSZ   64
#define MT    (BATCH*TSEQ)      // 4096 rows
#define EPSGN 0.00064f
#define NM    ((size_t)NEC*NEC) // 1M
#define HIDW  ((size_t)128*NEC) // one hidden weight slice
#define HME   ((size_t)MT*128)  // hidden matrix elems

// ---------------------------------------------------------------------------
// Scratch (device globals)
// ---------------------------------------------------------------------------
__device__ float    g_xx   [(size_t)MT*NEC];
__device__ uint32_t g_mixpk[(size_t)MT*NEC];   // packed (hi,lo) mix
__device__ float    g_hpart[4][HME];           // maa split-K partials
__device__ float    g_hmaa [HME];
__device__ float    g_hgate[HME];
__device__ float    g_hwaa [HME];              // decay(0:64) aaa(64:80) ma(80:96)
__device__ float    g_hk   [HME];              // kkk(0:16) mk(16:32)
__device__ uint32_t g_xm   [4][(size_t)MT*NEC]; // all packed (hi,lo) half2
__device__ __half   g_whalf[4*NM];             // Wr,Wk,Wv,Wo plain fp16
__device__ __half   g_whid [4*HIDW];           // hidden w1 slices fp16 (3) + maa_w1 (1)
__device__ uint32_t g_zpk  [(size_t)MT*NEC];
__device__ float    g_r    [(size_t)MT*NEC];
__device__ float    g_gg   [(size_t)MT*NEC];
__device__ float    g_k    [(size_t)MT*NEC];
__device__ float    g_v    [(size_t)MT*NEC];
__device__ float    g_w    [(size_t)MT*NEC];
__device__ float    g_kk   [(size_t)MT*NEC];
__device__ float    g_a    [(size_t)MT*NEC];
__device__ float    g_ma   [(size_t)MT*NEC];
__device__ float    g_mk   [(size_t)MT*NEC];
__device__ float    g_b    [(size_t)MT*NEC];
__device__ float    g_y    [(size_t)MT*NEC];

enum { EPI_NONE=0, EPI_W=3, EPI_SIG=5 };

// ---------------------------------------------------------------------------
// helpers
// ---------------------------------------------------------------------------
__device__ __forceinline__ uint32_t packf(float v){
    __half hi = __float2half_rn(v);
    __half lo = __float2half_rn(v - __half2float(hi));
    __half2 h2 = __halves2half2(hi, lo);
    return *reinterpret_cast<uint32_t*>(&h2);
}
__device__ __forceinline__ void mma_f16(float* c, const uint32_t* a, const uint32_t* b){
    asm volatile("mma.sync.aligned.m16n8k16.row.col.f32.f16.f16.f32 "
        "{%0,%1,%2,%3},{%4,%5,%6,%7},{%8,%9},{%0,%1,%2,%3};\n"
        : "+f"(c[0]), "+f"(c[1]), "+f"(c[2]), "+f"(c[3])
        : "r"(a[0]), "r"(a[1]), "r"(a[2]), "r"(a[3]), "r"(b[0]), "r"(b[1]));
}
__device__ __forceinline__ void cpa16(uint32_t dst, const void* src){
    asm volatile("cp.async.cg.shared.global [%0],[%1],16;\n"::"r"(dst),"l"(src));
}
__device__ __forceinline__ void cpa4(uint32_t dst, const void* src){
    asm volatile("cp.async.ca.shared.global [%0],[%1],4;\n"::"r"(dst),"l"(src));
}
#define CP_COMMIT() asm volatile("cp.async.commit_group;\n")
#define CP_WAIT0()  asm volatile("cp.async.wait_group 0;\n")
#define CP_WAIT1()  asm volatile("cp.async.wait_group 1;\n")

// ---------------------------------------------------------------------------
// Token shift (float4); mix written packed
// ---------------------------------------------------------------------------
__global__ void shift_kernel(const float* __restrict__ x,
                             const float* __restrict__ tmaax,
                             float* __restrict__ xx,
                             uint32_t* __restrict__ mixpk)
{
    size_t i4 = (size_t)blockIdx.x * blockDim.x + threadIdx.x;
    if (i4 >= (size_t)MT * NEC / 4) return;
    size_t idx = i4 * 4;
    int c = (int)(idx % NEC);
    size_t row = idx / NEC;
    int t = (int)(row % TSEQ);
    float4 xv = *(const float4*)&x[idx];
    float4 xp = (t > 0) ? *(const float4*)&x[idx - NEC] : make_float4(0,0,0,0);
    float4 tm = *(const float4*)&tmaax[c];
    float4 d  = make_float4(xp.x-xv.x, xp.y-xv.y, xp.z-xv.z, xp.w-xv.w);
    *(float4*)&xx[idx] = d;
    uint4 m;
    m.x = packf(fmaf(d.x, tm.x, xv.x));
    m.y = packf(fmaf(d.y, tm.y, xv.y));
    m.z = packf(fmaf(d.z, tm.z, xv.z));
    m.w = packf(fmaf(d.w, tm.w, xv.w));
    *(uint4*)&mixpk[idx] = m;
}

// ---------------------------------------------------------------------------
// Weight pack: Wr/Wk/Wv/Wo -> fp16 (half2 stores)
// ---------------------------------------------------------------------------
__global__ void wpack_kernel(const float* __restrict__ Wr, const float* __restrict__ Wk,
                             const float* __restrict__ Wv, const float* __restrict__ Wo,
                             __half* __restrict__ whalf)
{
    size_t i = (size_t)blockIdx.x * blockDim.x + threadIdx.x;   // 2 elems each
    if (i >= 2*NM) return;
    int seg = (int)(i >> 19);
    size_t off2 = (i & ((NM>>1) - 1)) * 2;
    const float* src = (seg==0) ? Wr : (seg==1) ? Wk : (seg==2) ? Wv : Wo;
    float2 v = *(const float2*)&src[off2];
    __half2 h = __halves2half2(__float2half_rn(v.x), __float2half_rn(v.y));
    *(__half2*)&whalf[(size_t)seg*NM + off2] = h;
}

// ---------------------------------------------------------------------------
// Hidden weight pack: 4 padded slices [128][1024] fp16
// ---------------------------------------------------------------------------
__global__ void wpack2_kernel(const float* __restrict__ gate_w1,
                              const float* __restrict__ decay_w1,
                              const float* __restrict__ aaa_w1,
                              const float* __restrict__ ma_w1,
                              const float* __restrict__ kkk_w1,
                              const float* __restrict__ mk_w1,
                              const float* __restrict__ maa_w1,
                              __half* __restrict__ whid)
{
    size_t i = (size_t)blockIdx.x * blockDim.x + threadIdx.x;
    if (i >= 4*HIDW) return;
    int slice = (int)(i / HIDW);
    size_t rem = i - (size_t)slice*HIDW;
    int row = (int)(rem >> 10);
    float v = 0.f;
    if (slice == 0) v = gate_w1[rem];
    else if (slice == 1) {
        if (row < 64)      v = decay_w1[rem];
        else if (row < 80) v = aaa_w1[rem - (size_t)64*NEC];
        else if (row < 96) v = ma_w1[rem - (size_t)80*NEC];
    } else if (slice == 2) {
        if (row < 16)      v = kkk_w1[rem];
        else if (row < 32) v = mk_w1[rem - (size_t)16*NEC];
    } else {
        v = maa_w1[rem];
    }
    whid[i] = __float2half_rn(v);
}

// ---------------------------------------------------------------------------
// Reduce + tanh for maa split-K partials
// ---------------------------------------------------------------------------
__global__ void hred_kernel(const float* __restrict__ hpart,
                            float* __restrict__ hmaa)
{
    size_t i4 = (size_t)blockIdx.x * blockDim.x + threadIdx.x;
    if (i4 >= HME/4) return;
    size_t idx = i4 * 4;
    float4 p0 = *(const float4*)&hpart[0*HME + idx];
    float4 p1 = *(const float4*)&hpart[1*HME + idx];
    float4 p2 = *(const float4*)&hpart[2*HME + idx];
    float4 p3 = *(const float4*)&hpart[3*HME + idx];
    float4 o;
    o.x = tanhf((p0.x+p1.x)+(p2.x+p3.x));
    o.y = tanhf((p0.y+p1.y)+(p2.y+p3.y));
    o.z = tanhf((p0.z+p1.z)+(p2.z+p3.z));
    o.w = tanhf((p0.w+p1.w)+(p2.w+p3.w));
    *(float4*)&hmaa[idx] = o;
}

// ---------------------------------------------------------------------------
// 2-product NT GEMM, TRIPLE-buffered: grid (gx, 32, nz + maybe-hidden).
//   z < nz: C[4096,1024] = (Ah+Al) * Bh^T
//   z >= nz: blockIdx.x = hidden slice 0..3 (others/null exit); N=128.
// ---------------------------------------------------------------------------
#define G5_LDSW 36
#define G5_AW   (128*G5_LDSW)
#define G5_LDHB 40
#define G5_BW   (128*G5_LDHB/2)
#define G5_STG  (G5_AW + G5_BW)
#define G5_NST  3

struct G5Args {
    const uint32_t* A[3]; const __half* B[3]; float* C[3];
    const uint32_t* HA[4]; const __half* HB[4]; float* HC[4]; int tanhN[4];
    int nz;
};

__global__ __launch_bounds__(256, 2)
void gemm_tc5(G5Args args, int K, int ldab)
{
    extern __shared__ uint32_t sm5[];
    const int z = blockIdx.z;
    const uint32_t* Apk; const __half* Bhp; float* C;
    int bn0, ldc, tanhN;
    if (z < args.nz) {
        Apk = args.A[z]; Bhp = args.B[z]; C = args.C[z];
        bn0 = blockIdx.x*128; ldc = NEC; tanhN = -1;
    } else {
        int s = blockIdx.x;
        if (s >= 4) return;
        Apk = args.HA[s]; Bhp = args.HB[s]; C = args.HC[s];
        if (!C) return;
        bn0 = 0; ldc = 128; tanhN = args.tanhN[s];
    }
    const int tid = threadIdx.x;
    const int bm0 = blockIdx.y*128;
    const int warp = tid>>5, lane = tid&31, grp = lane>>2, q = lane&3;
    const int wm = (warp&1)*64, wn = (warp>>1)*32;
    const uint32_t sbase = (uint32_t)__cvta_generic_to_shared(sm5);

    float acc[4][4][4];
    #pragma unroll
    for (int mi=0;mi<4;mi++)
        #pragma unroll
        for (int ni=0;ni<4;ni++)
            #pragma unroll
            for (int e=0;e<4;e++) acc[mi][ni][e]=0.f;

    const uint32_t* asrc[4]; uint32_t adst[4];
    #pragma unroll
    for (int l = 0; l < 4; l++) {
        int idx = tid + l*256;
        int r = idx >> 3, c4 = idx & 7;
        asrc[l] = Apk + (size_t)(bm0+r)*ldab + c4*4;
        adst[l] = sbase + (uint32_t)(r*G5_LDSW + c4*4)*4;
    }
    const __half* bsrc[2]; uint32_t bdst[2];
    #pragma unroll
    for (int l = 0; l < 2; l++) {
        int idx = tid + l*256;
        int r = idx >> 2, c4 = idx & 3;
        bsrc[l] = Bhp + (size_t)(bn0+r)*ldab + c4*8;
        bdst[l] = sbase + G5_AW*4 + (uint32_t)(r*G5_LDHB + c4*8)*2;
    }

#define G5_LOAD(st, kb) do {                                   \
        uint32_t _o = (st)*G5_STG*4;                           \
        _Pragma("unroll")                                      \
        for (int l = 0; l < 4; l++)                            \
            cpa16(adst[l] + _o, asrc[l] + (kb));               \
        _Pragma("unroll")                                      \
        for (int l = 0; l < 2; l++)                            \
            cpa16(bdst[l] + _o, bsrc[l] + (kb));               \
    } while(0)

    G5_LOAD(0, 0);  CP_COMMIT();
    if (32 < K) { G5_LOAD(1, 32); } CP_COMMIT();

    int p = 0;
    for (int kb = 0; kb < K; kb += 32) {
        CP_WAIT1();
        __syncthreads();
        {
            int pf = p + 2; if (pf >= G5_NST) pf -= G5_NST;
            if (kb + 64 < K) G5_LOAD(pf, kb+64);
            CP_COMMIT();
        }

        const uint32_t* SA = sm5 + p*G5_STG;
        const __half*   SB = (const __half*)(sm5 + p*G5_STG + G5_AW);

        #pragma unroll
        for (int kc = 0; kc < 32; kc += 16) {
            uint32_t ah[4][4], al[4][4], bh[4][2];
            #pragma unroll
            for (int mi = 0; mi < 4; mi++) {
                int r0 = (wm + mi*16 + grp)*G5_LDSW + kc + 2*q;
                uint2 w0 = *(const uint2*)&SA[r0];
                uint2 w1 = *(const uint2*)&SA[r0 + 8*G5_LDSW];
                uint2 w2 = *(const uint2*)&SA[r0 + 8];
                uint2 w3 = *(const uint2*)&SA[r0 + 8*G5_LDSW + 8];
                ah[mi][0]=__byte_perm(w0.x,w0.y,0x5410); al[mi][0]=__byte_perm(w0.x,w0.y,0x7632);
                ah[mi][1]=__byte_perm(w1.x,w1.y,0x5410); al[mi][1]=__byte_perm(w1.x,w1.y,0x7632);
                ah[mi][2]=__byte_perm(w2.x,w2.y,0x5410); al[mi][2]=__byte_perm(w2.x,w2.y,0x7632);
                ah[mi][3]=__byte_perm(w3.x,w3.y,0x5410); al[mi][3]=__byte_perm(w3.x,w3.y,0x7632);
            }
            #pragma unroll
            for (int ni = 0; ni < 4; ni++) {
                int c0 = (wn + ni*8 + grp)*G5_LDHB + kc + 2*q;
                bh[ni][0] = *(const uint32_t*)&SB[c0];
                bh[ni][1] = *(const uint32_t*)&SB[c0 + 8];
            }
            #pragma unroll
            for (int mi = 0; mi < 4; mi++)
                #pragma unroll
                for (int ni = 0; ni < 4; ni++) {
                    mma_f16(acc[mi][ni], ah[mi], bh[ni]);
                    mma_f16(acc[mi][ni], al[mi], bh[ni]);
                }
        }
        __syncthreads();
        if (++p == G5_NST) p = 0;
    }

    #pragma unroll
    for (int mi = 0; mi < 4; mi++) {
        int row0 = bm0 + wm + mi*16 + grp;
        #pragma unroll
        for (int ni = 0; ni < 4; ni++) {
            int col = bn0 + wn + ni*8 + 2*q;
            float e0 = acc[mi][ni][0], e1 = acc[mi][ni][1];
            float e2 = acc[mi][ni][2], e3 = acc[mi][ni][3];
            if (tanhN >= 0) {
                if (col   < tanhN) { e0 = tanhf(e0); e2 = tanhf(e2); }
                if (col+1 < tanhN) { e1 = tanhf(e1); e3 = tanhf(e3); }
            }
            *(float2*)&C[(size_t)row0*ldc + col]     = make_float2(e0, e1);
            *(float2*)&C[(size_t)(row0+8)*ldc + col] = make_float2(e2, e3);
        }
    }
#undef G5_LOAD
}

// ---------------------------------------------------------------------------
// Fused xm kernel: val = x + xx*(Ag @ Bg + time_maa[g]); all groups packed.
// ---------------------------------------------------------------------------
__global__ __launch_bounds__(256, 2)
void xm_kernel(const float* __restrict__ hmaa,
               const float* __restrict__ maa_w2,
               const float* __restrict__ x,
               const float* __restrict__ xx,
               const float* __restrict__ time_maa,
               uint32_t* __restrict__ xmbase)
{
    constexpr int BM=128, BN=128, BK=32;
    __shared__ float As[BK][BM+1];
    __shared__ float Bs[BK][BN];
    const int g = blockIdx.z;
    const float* A = hmaa + g*32;
    const float* B = maa_w2 + (size_t)g*32*NEC;
    uint32_t* C = xmbase + (size_t)g*MT*NEC;
    const float* tm = time_maa + g*NEC;
    const int bm0 = blockIdx.y*BM, bn0 = blockIdx.x*BN;
    const int tid = threadIdx.x;
    const int tx = tid & 15, ty = tid >> 4;

    float acc[8][8];
    #pragma unroll
    for (int i=0;i<8;i++)
        #pragma unroll
        for (int j=0;j<8;j++) acc[i][j]=0.f;

    #pragma unroll
    for (int l = 0; l < 4; l++) {
        int idx = tid + l*256;
        int r = idx >> 3, c = (idx & 7)*4;
        float4 val = *(const float4*)(A + (size_t)(bm0+r)*128 + c);
        As[c+0][r]=val.x; As[c+1][r]=val.y; As[c+2][r]=val.z; As[c+3][r]=val.w;
    }
    #pragma unroll
    for (int l = 0; l < 4; l++) {
        int idx = tid + l*256;
        int r = idx >> 5, c = (idx & 31)*4;
        *(float4*)&Bs[r][c] = *(const float4*)(B + (size_t)r*NEC + bn0 + c);
    }
    __syncthreads();
    #pragma unroll
    for (int kk = 0; kk < BK; kk++) {
        float rm[8], rn[8];
        #pragma unroll
        for (int i=0;i<8;i++) rm[i] = As[kk][ty*8+i];
        #pragma unroll
        for (int j=0;j<8;j++) rn[j] = Bs[kk][tx*8+j];
        #pragma unroll
        for (int i=0;i<8;i++)
            #pragma unroll
            for (int j=0;j<8;j++) acc[i][j] = fmaf(rm[i], rn[j], acc[i][j]);
    }
    #pragma unroll
    for (int i=0;i<8;i++) {
        int row = bm0 + ty*8 + i;
        #pragma unroll
        for (int j=0;j<8;j+=2) {
            int col = bn0 + tx*8 + j;
            size_t idx = (size_t)row*NEC + col;
            float2 xv = *(const float2*)&x[idx];
            float2 dv = *(const float2*)&xx[idx];
            float v0 = fmaf(dv.x, acc[i][j]   + tm[col],   xv.x);
            float v1 = fmaf(dv.y, acc[i][j+1] + tm[col+1], xv.y);
            *(uint2*)&C[idx] = make_uint2(packf(v0), packf(v1));
        }
    }
}

// ---------------------------------------------------------------------------
// Grouped second-stage NN kernel (A with lda + column offset)
// ---------------------------------------------------------------------------
struct NNGroup { const float* A; int lda; int koff; const float* B; float* C;
                 int K; int epi; const float* e2; };
struct NNArgs { NNGroup g[6]; };

__global__ __launch_bounds__(256)
void lora_nn_kernel(NNArgs args)
{
    constexpr int BM=128, BN=128, BK=16;
    __shared__ float As[BK][BM+1];
    __shared__ float Bs[BK][BN];
    NNGroup grp = args.g[blockIdx.z];
    const int K = grp.K;
    const int bm0 = blockIdx.y*BM, bn0 = blockIdx.x*BN;
    const int tid = threadIdx.x;
    const int tx = tid & 15, ty = tid >> 4;

    float acc[8][8];
    #pragma unroll
    for (int i=0;i<8;i++)
        #pragma unroll
        for (int j=0;j<8;j++) acc[i][j]=0.f;

    for (int kb = 0; kb < K; kb += BK) {
        #pragma unroll
        for (int l = 0; l < 2; l++) {
            int idx = tid + l*256;
            int r = idx >> 2, c = (idx & 3)*4;
            float4 val = *(const float4*)(grp.A + (size_t)(bm0+r)*grp.lda + grp.koff + kb + c);
            As[c+0][r]=val.x; As[c+1][r]=val.y; As[c+2][r]=val.z; As[c+3][r]=val.w;
        }
        #pragma unroll
        for (int l = 0; l < 2; l++) {
            int idx = tid + l*256;
            int r = idx >> 5, c = (idx & 31)*4;
            *(float4*)&Bs[r][c] = *(const float4*)(grp.B + (size_t)(kb+r)*NEC + bn0 + c);
        }
        __syncthreads();
        #pragma unroll
        for (int kk = 0; kk < BK; kk++) {
            float rm[8], rn[8];
            #pragma unroll
            for (int i=0;i<8;i++) rm[i] = As[kk][ty*8+i];
            #pragma unroll
            for (int j=0;j<8;j++) rn[j] = Bs[kk][tx*8+j];
            #pragma unroll
            for (int i=0;i<8;i++)
                #pragma unroll
                for (int j=0;j<8;j++) acc[i][j] = fmaf(rm[i], rn[j], acc[i][j]);
        }
        __syncthreads();
    }
    #pragma unroll
    for (int i=0;i<8;i++) {
        int row = bm0 + ty*8 + i;
        #pragma unroll
        for (int j=0;j<8;j++) {
            int col = bn0 + tx*8 + j;
            size_t idx = (size_t)row*NEC + col;
            float vv = acc[i][j], outv;
            switch (grp.epi) {
                case EPI_W: {
                    float tt = -(grp.e2[col] + vv);
                    float sp = (tt > 15.f) ? tt : log1pf(expf(tt));
                    outv = -sp - 0.5f;
                } break;
                case EPI_SIG: {
                    float u = grp.e2[col] + vv;
                    outv = 1.f / (1.f + expf(-u));
                } break;
                default: outv = vv;
            }
            grp.C[idx] = outv;
        }
    }
}

// ---------------------------------------------------------------------------
// warp sum
// ---------------------------------------------------------------------------
__device__ __forceinline__ float warp_sum(float v)
{
    #pragma unroll
    for (int o = 16; o > 0; o >>= 1) v += __shfl_xor_sync(0xffffffffu, v, o);
    return v;
}

// ---------------------------------------------------------------------------
// prep: kk = normalize(kkraw + k); b = -kk*a; k final; w transform
// ---------------------------------------------------------------------------
__global__ void prep_kernel(float* kptr, float* kkptr,
                            const float* __restrict__ a,
                            const float* __restrict__ ma,
                            const float* __restrict__ mk,
                            float* wptr,
                            float* __restrict__ b)
{
    int m = blockIdx.x;
    int h = threadIdx.x >> 5;
    int lane = threadIdx.x & 31;
    size_t base = (size_t)m*NEC + h*HSZ;
    size_t i0 = base + lane, i1 = i0 + 32;

    float k0v = kptr[i0], k1v = kptr[i1];
    float kk0 = kkptr[i0] + k0v, kk1 = kkptr[i1] + k1v;
    float ss = warp_sum(kk0*kk0 + kk1*kk1);
    float inv = 1.f / fmaxf(sqrtf(ss), 1e-12f);
    float n0 = kk0*inv, n1 = kk1*inv;
    kkptr[i0] = n0; kkptr[i1] = n1;

    float a0 = a[i0], a1 = a[i1];
    b[i0] = -n0*a0; b[i1] = -n1*a1;

    float ma0 = ma[i0], ma1 = ma[i1];
    float w0 = wptr[i0], w1 = wptr[i1];
    float mk0 = mk[i0], mk1 = mk[i1];
    kptr[i0] = k0v * (ma0 + a0*(1.f - ma0)) * expf(w0*mk0);
    kptr[i1] = k1v * (ma1 + a1*(1.f - ma1)) * expf(w1*mk1);
    wptr[i0] = expf(-expf(w0));
    wptr[i1] = expf(-expf(w1));
}

// ---------------------------------------------------------------------------
// RWKV7 recurrence v6: 2 blocks per head; 32 rows x 8-way column split;
// 3-QUAD cp.async ring, 4 steps per iteration (one sync / 4 steps).
// ---------------------------------------------------------------------------
__device__ __forceinline__ void wkv7_step(const float* __restrict__ bb,
                                          float* __restrict__ s,
                                          int il, int qd,
                                          float* __restrict__ yout)
{
    const int co = qd*8;
    const float4* q4 = (const float4*)(bb +   0 + co);
    const float4* w4 = (const float4*)(bb +  64 + co);
    const float4* k4 = (const float4*)(bb + 128 + co);
    const float4* a4 = (const float4*)(bb + 192 + co);
    const float4* b4 = (const float4*)(bb + 256 + co);
    float vi = bb[320 + il];

    float4 av0 = a4[0], av1 = a4[1];
    float sa0 = fmaf(s[0], av0.x, s[4]*av1.x);
    float sa1 = fmaf(s[1], av0.y, s[5]*av1.y);
    float sa2 = fmaf(s[2], av0.z, s[6]*av1.z);
    float sa3 = fmaf(s[3], av0.w, s[7]*av1.w);
    float sa = (sa0+sa1) + (sa2+sa3);
    sa += __shfl_xor_sync(0xffffffffu, sa, 1);
    sa += __shfl_xor_sync(0xffffffffu, sa, 2);
    sa += __shfl_xor_sync(0xffffffffu, sa, 4);

    float4 wv0 = w4[0], wv1 = w4[1];
    float4 kv0 = k4[0], kv1 = k4[1];
    float4 bv0 = b4[0], bv1 = b4[1];
    float4 qv0 = q4[0], qv1 = q4[1];

    float t0 = fmaf(s[0], wv0.x, fmaf(sa, bv0.x, vi*kv0.x));
    float t1 = fmaf(s[1], wv0.y, fmaf(sa, bv0.y, vi*kv0.y));
    float t2 = fmaf(s[2], wv0.z, fmaf(sa, bv0.z, vi*kv0.z));
    float t3 = fmaf(s[3], wv0.w, fmaf(sa, bv0.w, vi*kv0.w));
    float t4 = fmaf(s[4], wv1.x, fmaf(sa, bv1.x, vi*kv1.x));
    float t5 = fmaf(s[5], wv1.y, fmaf(sa, bv1.y, vi*kv1.y));
    float t6 = fmaf(s[6], wv1.z, fmaf(sa, bv1.z, vi*kv1.z));
    float t7 = fmaf(s[7], wv1.w, fmaf(sa, bv1.w, vi*kv1.w));
    s[0]=t0; s[1]=t1; s[2]=t2; s[3]=t3; s[4]=t4; s[5]=t5; s[6]=t6; s[7]=t7;

    float y0 = fmaf(t0, qv0.x, t4*qv1.x);
    float y1 = fmaf(t1, qv0.y, t5*qv1.y);
    float y2 = fmaf(t2, qv0.z, t6*qv1.z);
    float y3 = fmaf(t3, qv0.w, t7*qv1.w);
    float yi = (y0+y1) + (y2+y3);
    yi += __shfl_xor_sync(0xffffffffu, yi, 1);
    yi += __shfl_xor_sync(0xffffffffu, yi, 2);
    yi += __shfl_xor_sync(0xffffffffu, yi, 4);
    if (qd == 0) *yout = yi;
}

__global__ __launch_bounds__(256)
void wkv7_kernel(const float* __restrict__ q, const float* __restrict__ w,
                 const float* __restrict__ k, const float* __restrict__ v,
                 const float* __restrict__ a, const float* __restrict__ b,
                 float* __restrict__ y)
{
    const int blk = blockIdx.x;            // 0..127
    const int bh = blk >> 1, rh = blk & 1;
    const int batch = bh >> 4, h = bh & 15;
    const int tid = threadIdx.x;
    const int il = tid >> 3, qd = tid & 7;

    __shared__ __align__(16) float buf[3][1408];  // quad ring: 4 steps per quad

    float s[8];
    #pragma unroll
    for (int j = 0; j < 8; j++) s[j] = 0.f;

    const size_t base = (size_t)batch * TSEQ * NEC + (size_t)h * HSZ;

    const float* table[4] = {q, w, k, a};
    const float* s0 = table[tid>>6] + base + (tid & 63);
    const float* s1 = nullptr;
    if (tid < 64)       s1 = b + base + tid;
    else if (tid < 96)  s1 = v + base + rh*32 + (tid - 64);
    const uint32_t sb = (uint32_t)__cvta_generic_to_shared(buf);
    const uint32_t d0 = sb + (uint32_t)tid*4;
    const uint32_t d1 = sb + (uint32_t)(256 + tid)*4;
    const uint32_t QUADB = 1408*4;
    const uint32_t STEPB = 352*4;

    // prologue: quad0 = steps 0-3, quad1 = steps 4-7
    #pragma unroll
    for (int pr = 0; pr < 2; pr++) {
        #pragma unroll
        for (int st = 0; st < 4; st++) {
            size_t o = (size_t)(4*pr + st)*NEC;
            cpa4(d0 + pr*QUADB + st*STEPB, s0 + o);
            if (tid < 96) cpa4(d1 + pr*QUADB + st*STEPB, s1 + o);
        }
        CP_COMMIT();
    }

    const size_t ybase = base + (size_t)rh*32 + il;

    int pp = 0;
    for (int t = 0; t < TSEQ; t += 4) {
        CP_WAIT1();
        __syncthreads();

        {
            int pf = pp + 2; if (pf >= 3) pf -= 3;
            if (t + 8 < TSEQ) {
                uint32_t db = (uint32_t)pf*QUADB;
                #pragma unroll
                for (int st = 0; st < 4; st++) {
                    size_t o = (size_t)(t + 8 + st)*NEC;
                    cpa4(d0 + db + st*STEPB, s0 + o);
                    if (tid < 96) cpa4(d1 + db + st*STEPB, s1 + o);
                }
            }
            CP_COMMIT();
        }

        wkv7_step(&buf[pp][0],    s, il, qd, &y[ybase + (size_t)(t+0)*NEC]);
        wkv7_step(&buf[pp][352],  s, il, qd, &y[ybase + (size_t)(t+1)*NEC]);
        wkv7_step(&buf[pp][704],  s, il, qd, &y[ybase + (size_t)(t+2)*NEC]);
        wkv7_step(&buf[pp][1056], s, il, qd, &y[ybase + (size_t)(t+3)*NEC]);

        if (++pp == 3) pp = 0;
    }
}

// ---------------------------------------------------------------------------
// GroupNorm + bonus + gate -> packed z
// ---------------------------------------------------------------------------
__global__ void gn_kernel(const float* __restrict__ y,
                          const float* __restrict__ r,
                          const float* __restrict__ k,
                          const float* __restrict__ v,
                          const float* __restrict__ gg,
                          const float* __restrict__ ln_w,
                          const float* __restrict__ ln_b,
                          const float* __restrict__ faaaa,
                          uint32_t* __restrict__ zpk)
{
    int m = blockIdx.x;
    int h = threadIdx.x >> 5;
    int lane = threadIdx.x & 31;
    size_t base = (size_t)m*NEC + h*HSZ;
    int c0 = h*HSZ + lane, c1 = c0 + 32;
    size_t i0 = base + lane, i1 = i0 + 32;

    float y0 = y[i0], y1 = y[i1];
    float mu = warp_sum(y0 + y1) * (1.f/64.f);
    float d0 = y0 - mu, d1 = y1 - mu;
    float var = warp_sum(d0*d0 + d1*d1) * (1.f/64.f);
    float rstd = rsqrtf(var + EPSGN);
    float yn0 = d0*rstd*ln_w[c0] + ln_b[c0];
    float yn1 = d1*rstd*ln_w[c1] + ln_b[c1];

    float r0 = r[i0], r1 = r[i1];
    float k0v = k[i0], k1v = k[i1];
    float rk = warp_sum(r0*k0v*faaaa[c0] + r1*k1v*faaaa[c1]);

    float v0 = v[i0], v1 = v[i1];
    zpk[i0] = packf((yn0 + rk*v0) * gg[i0]);
    zpk[i1] = packf((yn1 + rk*v1) * gg[i1]);
}

// ---------------------------------------------------------------------------
// Host side
// ---------------------------------------------------------------------------
extern "C" void kernel_launch(void* const* d_in, const int* in_sizes, int n_in,
                              void* d_out, int out_size)
{
    const float* x          = (const float*)d_in[0];
    const float* time_maa_x = (const float*)d_in[1];
    const float* time_maa   = (const float*)d_in[2];
    const float* maa_w1     = (const float*)d_in[3];
    const float* maa_w2     = (const float*)d_in[4];
    const float* decay_w1   = (const float*)d_in[5];
    const float* decay_w2   = (const float*)d_in[6];
    const float* aaa_w1     = (const float*)d_in[7];
    const float* aaa_w2     = (const float*)d_in[8];
    const float* kkk_w1     = (const float*)d_in[9];
    const float* kkk_w2     = (const float*)d_in[10];
    const float* gate_w1    = (const float*)d_in[11];
    const float* gate_w2    = (const float*)d_in[12];
    const float* ma_w1      = (const float*)d_in[13];
    const float* ma_w2      = (const float*)d_in[14];
    const float* mk_w1      = (const float*)d_in[15];
    const float* mk_w2      = (const float*)d_in[16];
    const float* time_decay = (const float*)d_in[17];
    const float* time_faaaa = (const float*)d_in[18];
    const float* time_aaaaa = (const float*)d_in[19];
    const float* time_misc_a= (const float*)d_in[20];
    const float* time_misc_k= (const float*)d_in[21];
    const float* Wr         = (const float*)d_in[22];
    const float* Wk         = (const float*)d_in[23];
    const float* Wv         = (const float*)d_in[24];
    const float* Wo         = (const float*)d_in[25];
    const float* ln_w       = (const float*)d_in[26];
    const float* ln_b       = (const float*)d_in[27];
    float* out = (float*)d_out;

    float *xx,*hpart,*hmaa,*hgate,*hwaa,*hk;
    uint32_t *mixpk,*xm,*zpk; __half *whalf,*whid;
    float *r,*gg,*k,*v,*w,*kk,*a,*ma,*mk,*b,*y;
    cudaGetSymbolAddress((void**)&xx,   g_xx);
    cudaGetSymbolAddress((void**)&mixpk,g_mixpk);
    cudaGetSymbolAddress((void**)&hpart,g_hpart);
    cudaGetSymbolAddress((void**)&hmaa, g_hmaa);
    cudaGetSymbolAddress((void**)&hgate,g_hgate);
    cudaGetSymbolAddress((void**)&hwaa, g_hwaa);
    cudaGetSymbolAddress((void**)&hk,   g_hk);
    cudaGetSymbolAddress((void**)&xm,   g_xm);
    cudaGetSymbolAddress((void**)&whalf,g_whalf);
    cudaGetSymbolAddress((void**)&whid, g_whid);
    cudaGetSymbolAddress((void**)&zpk,  g_zpk);
    cudaGetSymbolAddress((void**)&r,    g_r);
    cudaGetSymbolAddress((void**)&gg,   g_gg);
    cudaGetSymbolAddress((void**)&k,    g_k);
    cudaGetSymbolAddress((void**)&v,    g_v);
    cudaGetSymbolAddress((void**)&w,    g_w);
    cudaGetSymbolAddress((void**)&kk,   g_kk);
    cudaGetSymbolAddress((void**)&a,    g_a);
    cudaGetSymbolAddress((void**)&ma,   g_ma);
    cudaGetSymbolAddress((void**)&mk,   g_mk);
    cudaGetSymbolAddress((void**)&b,    g_b);
    cudaGetSymbolAddress((void**)&y,    g_y);

    const size_t S = (size_t)MT*NEC;
    const uint32_t* xrg_pk = xm + 0*S;
    const uint32_t* xwa_pk = xm + 1*S;
    const uint32_t* xk_pk  = xm + 2*S;
    const uint32_t* xv_pk  = xm + 3*S;

    static bool attr_done = false;
    if (!attr_done) {
        cudaFuncSetAttribute(gemm_tc5, cudaFuncAttributeMaxDynamicSharedMemorySize,
                             G5_NST*G5_STG*4);
        attr_done = true;
    }
    const int g5_smem = G5_NST*G5_STG*4;

    // 1) token shift (mix packed)
    shift_kernel<<<(unsigned)((S/4 + 255)/256), 256>>>(x, time_maa_x, xx, mixpk);

    // 2) weight packs
    wpack_kernel<<<(unsigned)((2*NM + 255)/256), 256>>>(Wr, Wk, Wv, Wo, whalf);
    wpack2_kernel<<<(unsigned)((4*HIDW + 255)/256), 256>>>(
        gate_w1, decay_w1, aaa_w1, ma_w1, kkk_w1, mk_w1, maa_w1, whid);

    // 3) maa hidden split-K 4 -> partials, reduce+tanh
    {
        G5Args ga = {};
        ga.nz = 0;
        for (int sK = 0; sK < 4; sK++) {
            ga.HA[sK] = mixpk + sK*256;
            ga.HB[sK] = whid + 3*HIDW + sK*256;
            ga.HC[sK] = hpart + (size_t)sK*HME;
            ga.tanhN[sK] = -1;
        }
        gemm_tc5<<<dim3(4, 32, 1), 256, g5_smem>>>(ga, 256, NEC);
    }
    hred_kernel<<<(unsigned)((HME/4 + 255)/256), 256>>>(hpart, hmaa);

    // 4) xm fused (4 groups, all packed)
    xm_kernel<<<dim3(8, MT/128, 4), 256>>>(hmaa, maa_w2, x, xx, time_maa, xm);

    // 5) mega GEMM: r,k,v (z 0-2) + hidden slices (z 3)
    {
        G5Args ga = {};
        ga.nz = 3;
        ga.A[0] = xrg_pk; ga.B[0] = whalf + 0*NM; ga.C[0] = r;
        ga.A[1] = xk_pk;  ga.B[1] = whalf + 1*NM; ga.C[1] = k;
        ga.A[2] = xv_pk;  ga.B[2] = whalf + 2*NM; ga.C[2] = v;
        ga.HA[0] = xrg_pk; ga.HB[0] = whid + 0*HIDW; ga.HC[0] = hgate; ga.tanhN[0] = 128;
        ga.HA[1] = xwa_pk; ga.HB[1] = whid + 1*HIDW; ga.HC[1] = hwaa;  ga.tanhN[1] = 64;
        ga.HA[2] = xk_pk;  ga.HB[2] = whid + 2*HIDW; ga.HC[2] = hk;    ga.tanhN[2] = 16;
        ga.HC[3] = nullptr;
        gemm_tc5<<<dim3(8, 32, 4), 256, g5_smem>>>(ga, NEC, NEC);
    }

    // 6) second stage (6 groups from hidden slices)
    {
        NNArgs nn = {};
        nn.g[0] = { hgate, 128, 0,  gate_w2,  gg, 128, EPI_NONE, nullptr };
        nn.g[1] = { hwaa,  128, 0,  decay_w2, w,   64, EPI_W,    time_decay };
        nn.g[2] = { hk,    128, 0,  kkk_w2,   kk,  16, EPI_NONE, nullptr };
        nn.g[3] = { hwaa,  128, 64, aaa_w2,   a,   16, EPI_SIG,  time_aaaaa };
        nn.g[4] = { hwaa,  128, 80, ma_w2,    ma,  16, EPI_SIG,  time_misc_a };
        nn.g[5] = { hk,    128, 16, mk_w2,    mk,  16, EPI_SIG,  time_misc_k };
        lora_nn_kernel<<<dim3(8, MT/128, 6), 256>>>(nn);
    }

    // 7) prep (adds +k to kkraw before norm)
    prep_kernel<<<MT, 512>>>(k, kk, a, ma, mk, w, b);

    // 8) recurrence (quad-unrolled)
    wkv7_kernel<<<BATCH*NH*2, 256>>>(r, w, k, v, kk, b, y);

    // 9) groupnorm + bonus + gate -> packed z
    gn_kernel<<<MT, 512>>>(y, r, k, v, gg, ln_w, ln_b, time_faaaa, zpk);

    // 10) out = z @ Wo.T (2-product)
    {
        G5Args ga = {};
        ga.nz = 1;
        ga.A[0] = zpk; ga.B[0] = whalf + 3*NM; ga.C[0] = out;
        gemm_tc5<<<dim3(8, 32, 1), 256, g5_smem>>>(ga, NEC, NEC);
    }
}